// round 11
// baseline (speedup 1.0000x reference)
#include <cuda_runtime.h>
#include <cuda_fp16.h>
#include <cstdint>

#define NN 524288   // nodes
#define DD 256      // input dim
#define HH 128      // hidden dim
#define BB 2048     // segments

// ---------------- scratch (device globals; no allocation allowed) ----------
__device__ float    g_wts[NN];          // exp(score), unnormalized
__device__ float    g_segsum[BB];       // sum of exp per segment (atomics)
__device__ uint32_t g_w1ph[(DD / 2) * HH];  // permuted half2 W1

// ---------------- helpers ---------------------------------------------------
__device__ __forceinline__ float tanha(float x) {
    float y;
    asm("tanh.approx.f32 %0, %1;" : "=f"(y) : "f"(x));
    return y;
}
__device__ __forceinline__ uint32_t smem_u32(const void* p) {
    uint32_t a;
    asm("{ .reg .u64 t; cvta.to.shared.u64 t, %1; cvt.u32.u64 %0, t; }" : "=r"(a) : "l"(p));
    return a;
}
__device__ __forceinline__ uint32_t pack_h2(float lo, float hi) {
    __half2 h = __floats2half2_rn(lo, hi);
    return *(uint32_t*)&h;
}
#define CP16(dst, src)  asm volatile("cp.async.ca.shared.global [%0], [%1], 16;" :: "r"(dst), "l"(src) : "memory")
#define CP_COMMIT()     asm volatile("cp.async.commit_group;" ::: "memory")
#define CP_WAIT(n)      asm volatile("cp.async.wait_group %0;" :: "n"(n) : "memory")

__device__ __forceinline__ void mma_f16(float& c0, float& c1, float& c2, float& c3,
                                        uint32_t a0, uint32_t a1, uint32_t a2, uint32_t a3,
                                        uint32_t b0, uint32_t b1) {
    asm("mma.sync.aligned.m16n8k16.row.col.f32.f16.f16.f32 "
        "{%0,%1,%2,%3}, {%4,%5,%6,%7}, {%8,%9}, {%0,%1,%2,%3};"
        : "+f"(c0), "+f"(c1), "+f"(c2), "+f"(c3)
        : "r"(a0), "r"(a1), "r"(a2), "r"(a3), "r"(b0), "r"(b1));
}

// ---------------- kernel Z: zero out + segsum (one-shot per run) ------------
__global__ void zero_kernel(float* __restrict__ out) {
    out[(size_t)blockIdx.x * DD + threadIdx.x] = 0.0f;
    if (threadIdx.x == 0) g_segsum[blockIdx.x] = 0.0f;
}

// ---------------- kernel 0: W1 -> permuted packed half2 (one-shot) ---------
__global__ void w1h_kernel(const float* __restrict__ W1) {
    int k2 = blockIdx.x;         // 0..127
    int c  = threadIdx.x;        // 0..127
    g_w1ph[k2 * HH + (c & 7) * 16 + (c >> 3)] =
        pack_h2(W1[(2 * k2) * HH + c], W1[(2 * k2 + 1) * HH + c]);
}

// ---------------- kernel A: wts = exp(tanh(x@W1+b1)@W2+b2); segsum atomics --
// fp16 m16n8k16. 256 threads, 2 CTAs/SM. CTA tile: 128 nodes x 128 cols.
// Warp tile: 32 nodes x 64 cols. Single barrier per k-chunk.
#define KC 32
#define K2C 16
#define XS_STRIDE  20
#define W1P_STRIDE 132
#define XBUF_B  (128 * XS_STRIDE * 4)   // 10240 B
#define W1BUF_B (K2C * W1P_STRIDE * 4)  // 8448 B
#define OFF_X    0
#define OFF_W1   (2 * XBUF_B)            // 20480
#define OFF_B1   (OFF_W1 + 2 * W1BUF_B)  // 37376
#define OFF_W2   (OFF_B1 + 512)
#define OFF_PART (OFF_W2 + 512)
#define OFF_B2   (OFF_PART + 512)
#define SMEM_A_BYTES (OFF_B2 + 16)       // ~38.9 KB (2 CTAs -> ~78 KB/SM)

__global__ void __launch_bounds__(256, 2)
scores_kernel(const float* __restrict__ x,
              const int* __restrict__ batch,
              const float* __restrict__ b1,
              const float* __restrict__ W2,
              const float* __restrict__ b2) {
    extern __shared__ char smem[];
    const uint32_t sb = smem_u32(smem);

    float* b1s  = (float*)(smem + OFF_B1);
    float* w2s  = (float*)(smem + OFF_W2);
    float* part = (float*)(smem + OFF_PART);

    const int tid  = threadIdx.x;
    const int lane = tid & 31;
    const int wid  = tid >> 5;
    const int t    = lane & 3;          // k2 row within group
    const int g    = lane >> 2;         // group id
    const int wn   = (wid & 3) * 32;    // warp node base
    const int chf  = wid >> 2;          // column half
    const int n0   = blockIdx.x * 128;

    if (tid < 128) { b1s[tid] = b1[tid]; w2s[tid] = W2[tid]; }
    if (tid == 0)  { ((float*)(smem + OFF_B2))[0] = b2[0]; }

    float acc[2][8][4];
    #pragma unroll
    for (int ra = 0; ra < 2; ++ra)
        #pragma unroll
        for (int j = 0; j < 8; ++j)
            #pragma unroll
            for (int r = 0; r < 4; ++r) acc[ra][j][r] = 0.0f;

    const float4* x4   = (const float4*)x;
    const char*   wsrc = (const char*)g_w1ph;

    // staging decompositions
    const int xnode = tid >> 1, xjj = tid & 1;  // x: node, j' = xjj + 2i
    const int wrow  = tid >> 5, wq  = tid & 31; // W1: +tt*8 k2-rows, 16B group

    // ---- prologue: cp.async W1 chunk 0 -> buf0; LDG x chunk 0 ----
    #pragma unroll
    for (int tt = 0; tt < 2; ++tt) {
        int row = wrow + tt * 8;
        CP16(sb + OFF_W1 + (uint32_t)(row * W1P_STRIDE + 4 * wq) * 4,
             wsrc + (size_t)(row * HH + 4 * wq) * 4);
    }
    CP_COMMIT();

    float4 rx[4];
    #pragma unroll
    for (int i = 0; i < 2; ++i) {
        int jp = xjj + 2 * i;
        rx[2 * i]     = x4[(size_t)(n0 + xnode) * 64 + 2 * jp];
        rx[2 * i + 1] = x4[(size_t)(n0 + xnode) * 64 + 2 * jp + 1];
    }

    for (int ch = 0; ch < 8; ++ch) {
        const int buf = ch & 1;
        uint32_t* xb  = (uint32_t*)(smem + OFF_X  + buf * XBUF_B);
        uint32_t* w1b = (uint32_t*)(smem + OFF_W1 + buf * W1BUF_B);

        // ---- store staged x chunk (cvt to half2, STS.128) ----
        #pragma unroll
        for (int i = 0; i < 2; ++i) {
            int jp = xjj + 2 * i;
            float4 f0 = rx[2 * i], f1 = rx[2 * i + 1];
            uint4 u;
            u.x = pack_h2(f0.x, f0.y); u.y = pack_h2(f0.z, f0.w);
            u.z = pack_h2(f1.x, f1.y); u.w = pack_h2(f1.z, f1.w);
            *(uint4*)(xb + xnode * XS_STRIDE + 4 * jp) = u;
        }
        CP_WAIT(0);          // W1(buf) resident
        __syncthreads();     // STS visible; prior chunk's compute finished

        // issue NEXT chunk's loads only after the barrier (no WAR race)
        if (ch < 7) {
            const uint32_t wo = OFF_W1 + (buf ^ 1) * W1BUF_B;
            #pragma unroll
            for (int tt = 0; tt < 2; ++tt) {
                int row = wrow + tt * 8;
                CP16(sb + wo + (uint32_t)(row * W1P_STRIDE + 4 * wq) * 4,
                     wsrc + (size_t)(((ch + 1) * K2C + row) * HH + 4 * wq) * 4);
            }
            CP_COMMIT();
            #pragma unroll
            for (int i = 0; i < 2; ++i) {
                int jp = xjj + 2 * i;
                rx[2 * i]     = x4[(size_t)(n0 + xnode) * 64 + (ch + 1) * 8 + 2 * jp];
                rx[2 * i + 1] = x4[(size_t)(n0 + xnode) * 64 + (ch + 1) * 8 + 2 * jp + 1];
            }
        }

        // ---- compute 2 k-steps (K=16 each) ----
        #pragma unroll
        for (int ks = 0; ks < 2; ++ks) {
            const int k2l = ks * 8;
            uint32_t ax[2][4];
            #pragma unroll
            for (int ra = 0; ra < 2; ++ra) {
                const uint32_t* xr = xb + (wn + 16 * ra + g) * XS_STRIDE + k2l;
                ax[ra][0] = xr[t];
                ax[ra][1] = xr[8 * XS_STRIDE + t];
                ax[ra][2] = xr[t + 4];
                ax[ra][3] = xr[8 * XS_STRIDE + t + 4];
            }
            const uint32_t* r0 = w1b + (k2l + t) * W1P_STRIDE + g * 16 + chf * 8;
            const uint32_t* r1 = r0 + 4 * W1P_STRIDE;
            uint4 u0 = *(const uint4*)(r0);
            uint4 u1 = *(const uint4*)(r0 + 4);
            uint4 v0 = *(const uint4*)(r1);
            uint4 v1 = *(const uint4*)(r1 + 4);
            uint32_t bu[8] = {u0.x, u0.y, u0.z, u0.w, u1.x, u1.y, u1.z, u1.w};
            uint32_t bv[8] = {v0.x, v0.y, v0.z, v0.w, v1.x, v1.y, v1.z, v1.w};

            #pragma unroll
            for (int ra = 0; ra < 2; ++ra) {
                #pragma unroll
                for (int j = 0; j < 8; ++j) {
                    mma_f16(acc[ra][j][0], acc[ra][j][1], acc[ra][j][2], acc[ra][j][3],
                            ax[ra][0], ax[ra][1], ax[ra][2], ax[ra][3],
                            bu[j], bv[j]);
                }
            }
        }
        // no trailing barrier: iter ch+2's writes are separated from iter ch's
        // reads by iter ch+1's barrier (program order per thread).
    }

    // ---- epilogue: +b1, tanh, dot W2, reduce, exp, segment-sum atomics ----
    float p[4] = {0.f, 0.f, 0.f, 0.f};
    #pragma unroll
    for (int ra = 0; ra < 2; ++ra) {
        #pragma unroll
        for (int j = 0; j < 8; ++j) {
            #pragma unroll
            for (int rr = 0; rr < 2; ++rr) {
                int cc = (chf * 8 + j) * 8 + 2 * t + rr;
                float bb = b1s[cc], ww = w2s[cc];
                p[2 * ra]     += tanha(acc[ra][j][rr]     + bb) * ww;
                p[2 * ra + 1] += tanha(acc[ra][j][2 + rr] + bb) * ww;
            }
        }
    }
    #pragma unroll
    for (int i = 0; i < 4; ++i) {
        p[i] += __shfl_xor_sync(0xffffffffu, p[i], 1);
        p[i] += __shfl_xor_sync(0xffffffffu, p[i], 2);
    }
    __syncthreads();   // smem reads of chunk 7 done before part[] overwrites xs region? (part is separate; barrier orders part writes vs reads below)
    if (t == 0 && chf == 0) {
        part[wn + g]      = p[0];
        part[wn + g + 8]  = p[1];
        part[wn + g + 16] = p[2];
        part[wn + g + 24] = p[3];
    }
    __syncthreads();
    if (t == 0 && chf == 1) {
        float bb2 = ((float*)(smem + OFF_B2))[0];
        #pragma unroll
        for (int i = 0; i < 4; ++i) {
            int node = wn + g + 8 * i;
            float score = part[node] + p[i] + bb2;
            float e = expf(score);
            g_wts[n0 + node] = e;
            atomicAdd(&g_segsum[batch[n0 + node]], e);
        }
    }
}

// ---------------- kernel C: balanced pooling with atomics -------------------
// 4096 blocks x 128 nodes each; thread = dim. Segment boundaries inside the
// block found from the sorted batch; partial sums flushed via atomicAdd.
__device__ __forceinline__ int lb128(const int* __restrict__ seg, int v) {
    int lo = 0, hi = 128;
    while (lo < hi) {
        int mid = (lo + hi) >> 1;
        if (seg[mid] < v) lo = mid + 1; else hi = mid;
    }
    return lo;
}

__global__ void __launch_bounds__(256)
pool_kernel(const float* __restrict__ x,
            const int* __restrict__ batch,
            float* __restrict__ out) {
    const int base = blockIdx.x * 128;
    const int tid  = threadIdx.x;
    __shared__ int   seg[128];
    __shared__ float w[128];

    if (tid < 128) {
        int s = batch[base + tid];
        seg[tid] = s;
        w[tid] = __fdividef(g_wts[base + tid], g_segsum[s]);
    }
    __syncthreads();

    const int s0 = seg[0], s1 = seg[127];
    const float* xp = x + (size_t)base * DD + tid;

    if (s0 == s1) {
        // common case: whole block in one segment
        float acc = 0.0f;
        #pragma unroll 8
        for (int j = 0; j < 128; ++j)
            acc += xp[(size_t)j * DD] * w[j];
        atomicAdd(&out[(size_t)s0 * DD + tid], acc);
    } else {
        for (int s = s0; s <= s1; ++s) {
            int jlo = lb128(seg, s);
            int jhi = lb128(seg, s + 1);
            if (jhi <= jlo) continue;
            float acc = 0.0f;
            int j = jlo;
            for (; j + 4 <= jhi; j += 4) {
                float v0 = xp[(size_t)(j + 0) * DD];
                float v1 = xp[(size_t)(j + 1) * DD];
                float v2 = xp[(size_t)(j + 2) * DD];
                float v3 = xp[(size_t)(j + 3) * DD];
                acc += v0 * w[j + 0]; acc += v1 * w[j + 1];
                acc += v2 * w[j + 2]; acc += v3 * w[j + 3];
            }
            for (; j < jhi; ++j) acc += xp[(size_t)j * DD] * w[j];
            atomicAdd(&out[(size_t)s * DD + tid], acc);
        }
    }
}

// ---------------- launch ------------------------------------------------------
extern "C" void kernel_launch(void* const* d_in, const int* in_sizes, int n_in,
                              void* d_out, int out_size) {
    (void)in_sizes; (void)n_in; (void)out_size;
    const float* x     = (const float*)d_in[0];
    const int*   batch = (const int*)d_in[1];
    const float* W1    = (const float*)d_in[2];
    const float* b1    = (const float*)d_in[3];
    const float* W2    = (const float*)d_in[4];
    const float* b2    = (const float*)d_in[5];
    float*       out   = (float*)d_out;

    cudaFuncSetAttribute(scores_kernel,
                         cudaFuncAttributeMaxDynamicSharedMemorySize,
                         SMEM_A_BYTES);

    zero_kernel<<<BB, DD>>>(out);
    w1h_kernel<<<DD / 2, HH>>>(W1);
    scores_kernel<<<NN / 128, 256, SMEM_A_BYTES>>>(x, batch, b1, W2, b2);
    pool_kernel<<<NN / 128, 256>>>(x, batch, out);
}

// round 12
// speedup vs baseline: 1.2517x; 1.2517x over previous
#include <cuda_runtime.h>
#include <cuda_fp16.h>
#include <cstdint>

#define NN 524288   // nodes
#define DD 256      // input dim
#define HH 128      // hidden dim
#define BB 2048     // segments

// ---------------- scratch (device globals; no allocation allowed) ----------
__device__ float    g_wts[NN];          // exp(score), unnormalized
__device__ float    g_segsum[BB];       // per-segment sum of exp (atomics)
__device__ uint32_t g_w1ph[(DD / 2) * HH];  // permuted half2 W1

// ---------------- helpers ---------------------------------------------------
__device__ __forceinline__ float tanha(float x) {
    float y;
    asm("tanh.approx.f32 %0, %1;" : "=f"(y) : "f"(x));
    return y;
}
__device__ __forceinline__ uint32_t smem_u32(const void* p) {
    uint32_t a;
    asm("{ .reg .u64 t; cvta.to.shared.u64 t, %1; cvt.u32.u64 %0, t; }" : "=r"(a) : "l"(p));
    return a;
}
__device__ __forceinline__ uint32_t pack_h2(float lo, float hi) {
    __half2 h = __floats2half2_rn(lo, hi);
    return *(uint32_t*)&h;
}
#define CP16(dst, src)  asm volatile("cp.async.ca.shared.global [%0], [%1], 16;" :: "r"(dst), "l"(src) : "memory")
#define CP_COMMIT()     asm volatile("cp.async.commit_group;" ::: "memory")
#define CP_WAIT(n)      asm volatile("cp.async.wait_group %0;" :: "n"(n) : "memory")

__device__ __forceinline__ void mma_f16(float& c0, float& c1, float& c2, float& c3,
                                        uint32_t a0, uint32_t a1, uint32_t a2, uint32_t a3,
                                        uint32_t b0, uint32_t b1) {
    asm("mma.sync.aligned.m16n8k16.row.col.f32.f16.f16.f32 "
        "{%0,%1,%2,%3}, {%4,%5,%6,%7}, {%8,%9}, {%0,%1,%2,%3};"
        : "+f"(c0), "+f"(c1), "+f"(c2), "+f"(c3)
        : "r"(a0), "r"(a1), "r"(a2), "r"(a3), "r"(b0), "r"(b1));
}

// ---------------- kernel Z: zero g_segsum (cheap, graph-replay safe) --------
__global__ void zseg_kernel() {
    g_segsum[blockIdx.x * 256 + threadIdx.x] = 0.0f;
}

// ---------------- kernel 0: W1 -> permuted packed half2 (one-shot) ---------
__global__ void w1h_kernel(const float* __restrict__ W1) {
    int k2 = blockIdx.x;         // 0..127
    int c  = threadIdx.x;        // 0..127
    g_w1ph[k2 * HH + (c & 7) * 16 + (c >> 3)] =
        pack_h2(W1[(2 * k2) * HH + c], W1[(2 * k2 + 1) * HH + c]);
}

// ---------------- kernel A: wts = exp(tanh(x@W1+b1)@W2+b2) + segsum atomics -
// EXACT R10 loop structure (two barriers, CP_WAIT(1)). fp16 m16n8k16.
// 256 threads (8 warps), 2 CTAs/SM. CTA tile: 128 nodes x 128 cols.
// Warp tile: 32 nodes x 64 cols. wid&3 = node slice, wid>>2 = column half.
#define KC 32
#define K2C 16
#define XS_STRIDE  20
#define W1P_STRIDE 132
#define XBUF_B  (128 * XS_STRIDE * 4)   // 10240 B
#define W1BUF_B (K2C * W1P_STRIDE * 4)  // 8448 B
#define OFF_X    0
#define OFF_W1   (2 * XBUF_B)            // 20480
#define OFF_B1   (OFF_W1 + 2 * W1BUF_B)  // 37376
#define OFF_W2   (OFF_B1 + 512)
#define OFF_PART (OFF_W2 + 512)
#define OFF_B2   (OFF_PART + 512)
#define SMEM_A_BYTES (OFF_B2 + 16)       // ~38.9 KB (2 CTAs -> ~78 KB/SM)

__global__ void __launch_bounds__(256, 2)
scores_kernel(const float* __restrict__ x,
              const int* __restrict__ batch,
              const float* __restrict__ b1,
              const float* __restrict__ W2,
              const float* __restrict__ b2) {
    extern __shared__ char smem[];
    const uint32_t sb = smem_u32(smem);

    float* b1s  = (float*)(smem + OFF_B1);
    float* w2s  = (float*)(smem + OFF_W2);
    float* part = (float*)(smem + OFF_PART);

    const int tid  = threadIdx.x;
    const int lane = tid & 31;
    const int wid  = tid >> 5;
    const int t    = lane & 3;          // k2 row within group
    const int g    = lane >> 2;         // group id
    const int wn   = (wid & 3) * 32;    // warp node base
    const int chf  = wid >> 2;          // column half
    const int n0   = blockIdx.x * 128;

    if (tid < 128) { b1s[tid] = b1[tid]; w2s[tid] = W2[tid]; }
    if (tid == 0)  { ((float*)(smem + OFF_B2))[0] = b2[0]; }

    float acc[2][8][4];
    #pragma unroll
    for (int ra = 0; ra < 2; ++ra)
        #pragma unroll
        for (int j = 0; j < 8; ++j)
            #pragma unroll
            for (int r = 0; r < 4; ++r) acc[ra][j][r] = 0.0f;

    const float4* x4   = (const float4*)x;
    const char*   wsrc = (const char*)g_w1ph;

    // staging decompositions
    const int xnode = tid >> 1, xjj = tid & 1;  // x: node, j' = xjj + 2i
    const int wrow  = tid >> 5, wq  = tid & 31; // W1: +tt*8 k2-rows, 16B group

    // ---- prologue: cp.async W1 chunk 0; prefetch x chunk 0 ----
    #pragma unroll
    for (int tt = 0; tt < 2; ++tt) {
        int row = wrow + tt * 8;
        CP16(sb + OFF_W1 + (uint32_t)(row * W1P_STRIDE + 4 * wq) * 4,
             wsrc + (size_t)(row * HH + 4 * wq) * 4);
    }
    CP_COMMIT();

    float4 rx[4];
    #pragma unroll
    for (int i = 0; i < 2; ++i) {
        int jp = xjj + 2 * i;
        rx[2 * i]     = x4[(size_t)(n0 + xnode) * 64 + 2 * jp];
        rx[2 * i + 1] = x4[(size_t)(n0 + xnode) * 64 + 2 * jp + 1];
    }

    for (int ch = 0; ch < 8; ++ch) {
        const int buf = ch & 1;
        uint32_t* xb  = (uint32_t*)(smem + OFF_X  + buf * XBUF_B);
        uint32_t* w1b = (uint32_t*)(smem + OFF_W1 + buf * W1BUF_B);

        // ---- store staged x chunk (cvt to half2, STS.128) ----
        #pragma unroll
        for (int i = 0; i < 2; ++i) {
            int jp = xjj + 2 * i;
            float4 f0 = rx[2 * i], f1 = rx[2 * i + 1];
            uint4 u;
            u.x = pack_h2(f0.x, f0.y); u.y = pack_h2(f0.z, f0.w);
            u.z = pack_h2(f1.x, f1.y); u.w = pack_h2(f1.z, f1.w);
            *(uint4*)(xb + xnode * XS_STRIDE + 4 * jp) = u;
        }

        // ---- issue next chunk's loads ----
        if (ch < 7) {
            const uint32_t wo = OFF_W1 + (buf ^ 1) * W1BUF_B;
            #pragma unroll
            for (int tt = 0; tt < 2; ++tt) {
                int row = wrow + tt * 8;
                CP16(sb + wo + (uint32_t)(row * W1P_STRIDE + 4 * wq) * 4,
                     wsrc + (size_t)(((ch + 1) * K2C + row) * HH + 4 * wq) * 4);
            }
            CP_COMMIT();
            #pragma unroll
            for (int i = 0; i < 2; ++i) {
                int jp = xjj + 2 * i;
                rx[2 * i]     = x4[(size_t)(n0 + xnode) * 64 + (ch + 1) * 8 + 2 * jp];
                rx[2 * i + 1] = x4[(size_t)(n0 + xnode) * 64 + (ch + 1) * 8 + 2 * jp + 1];
            }
            CP_WAIT(1);   // chunk ch's W1 complete; ch+1 in flight
        } else {
            CP_WAIT(0);
        }
        __syncthreads();

        // ---- compute 2 k-steps (K=16 each) ----
        #pragma unroll
        for (int ks = 0; ks < 2; ++ks) {
            const int k2l = ks * 8;
            uint32_t ax[2][4];
            #pragma unroll
            for (int ra = 0; ra < 2; ++ra) {
                const uint32_t* xr = xb + (wn + 16 * ra + g) * XS_STRIDE + k2l;
                ax[ra][0] = xr[t];
                ax[ra][1] = xr[8 * XS_STRIDE + t];
                ax[ra][2] = xr[t + 4];
                ax[ra][3] = xr[8 * XS_STRIDE + t + 4];
            }
            const uint32_t* r0 = w1b + (k2l + t) * W1P_STRIDE + g * 16 + chf * 8;
            const uint32_t* r1 = r0 + 4 * W1P_STRIDE;
            uint4 u0 = *(const uint4*)(r0);
            uint4 u1 = *(const uint4*)(r0 + 4);
            uint4 v0 = *(const uint4*)(r1);
            uint4 v1 = *(const uint4*)(r1 + 4);
            uint32_t bu[8] = {u0.x, u0.y, u0.z, u0.w, u1.x, u1.y, u1.z, u1.w};
            uint32_t bv[8] = {v0.x, v0.y, v0.z, v0.w, v1.x, v1.y, v1.z, v1.w};

            #pragma unroll
            for (int ra = 0; ra < 2; ++ra) {
                #pragma unroll
                for (int j = 0; j < 8; ++j) {
                    mma_f16(acc[ra][j][0], acc[ra][j][1], acc[ra][j][2], acc[ra][j][3],
                            ax[ra][0], ax[ra][1], ax[ra][2], ax[ra][3],
                            bu[j], bv[j]);
                }
            }
        }
        __syncthreads();
    }

    // ---- epilogue: +b1, tanh, dot W2, reduce, exp, segsum atomics ----
    float p[4] = {0.f, 0.f, 0.f, 0.f};
    #pragma unroll
    for (int ra = 0; ra < 2; ++ra) {
        #pragma unroll
        for (int j = 0; j < 8; ++j) {
            #pragma unroll
            for (int rr = 0; rr < 2; ++rr) {
                int cc = (chf * 8 + j) * 8 + 2 * t + rr;
                float bb = b1s[cc], ww = w2s[cc];
                p[2 * ra]     += tanha(acc[ra][j][rr]     + bb) * ww;
                p[2 * ra + 1] += tanha(acc[ra][j][2 + rr] + bb) * ww;
            }
        }
    }
    #pragma unroll
    for (int i = 0; i < 4; ++i) {
        p[i] += __shfl_xor_sync(0xffffffffu, p[i], 1);
        p[i] += __shfl_xor_sync(0xffffffffu, p[i], 2);
    }
    if (t == 0 && chf == 0) {
        part[wn + g]      = p[0];
        part[wn + g + 8]  = p[1];
        part[wn + g + 16] = p[2];
        part[wn + g + 24] = p[3];
    }
    __syncthreads();
    if (t == 0 && chf == 1) {
        float bb2 = ((float*)(smem + OFF_B2))[0];
        #pragma unroll
        for (int i = 0; i < 4; ++i) {
            int node = wn + g + 8 * i;
            float score = part[node] + p[i] + bb2;
            float e = expf(score);   // safe unshifted: |score| <= ~11.4
            g_wts[n0 + node] = e;
            atomicAdd(&g_segsum[batch[n0 + node]], e);
        }
    }
}

// ---------------- binary search ---------------------------------------------
__device__ __forceinline__ int lower_bound_i32(const int* __restrict__ a, int n, int v) {
    int lo = 0, hi = n;
    while (lo < hi) {
        int mid = (lo + hi) >> 1;
        if (a[mid] < v) lo = mid + 1; else hi = mid;
    }
    return lo;
}

// ---------------- kernel C: pooled[b,d] = sum_i x[i,d] * w_i (R5 form) ------
__global__ void pool_kernel(const float* __restrict__ x,
                            const int* __restrict__ batch,
                            float* __restrict__ out) {
    const int b = blockIdx.x;
    const int tid = threadIdx.x;   // dim d
    __shared__ int se[2];
    __shared__ float ws[256];

    if (tid == 0) {
        se[0] = lower_bound_i32(batch, NN, b);
        se[1] = lower_bound_i32(batch, NN, b + 1);
    }
    __syncthreads();
    const int st = se[0], en = se[1];
    const float Z = g_segsum[b];
    const float invZ = (en > st && Z > 0.0f) ? (1.0f / Z) : 0.0f;

    float acc = 0.0f;
    for (int i0 = st; i0 < en; i0 += 256) {
        int cnt = min(256, en - i0);
        __syncthreads();
        if (tid < cnt) ws[tid] = g_wts[i0 + tid] * invZ;
        __syncthreads();
        const float* xp = x + (size_t)i0 * DD + tid;
        int j = 0;
        for (; j + 8 <= cnt; j += 8) {
            float v0 = xp[(size_t)(j + 0) * DD];
            float v1 = xp[(size_t)(j + 1) * DD];
            float v2 = xp[(size_t)(j + 2) * DD];
            float v3 = xp[(size_t)(j + 3) * DD];
            float v4 = xp[(size_t)(j + 4) * DD];
            float v5 = xp[(size_t)(j + 5) * DD];
            float v6 = xp[(size_t)(j + 6) * DD];
            float v7 = xp[(size_t)(j + 7) * DD];
            acc += v0 * ws[j + 0]; acc += v1 * ws[j + 1];
            acc += v2 * ws[j + 2]; acc += v3 * ws[j + 3];
            acc += v4 * ws[j + 4]; acc += v5 * ws[j + 5];
            acc += v6 * ws[j + 6]; acc += v7 * ws[j + 7];
        }
        for (; j < cnt; ++j) acc += xp[(size_t)j * DD] * ws[j];
    }
    out[(size_t)b * DD + tid] = acc;
}

// ---------------- launch ------------------------------------------------------
extern "C" void kernel_launch(void* const* d_in, const int* in_sizes, int n_in,
                              void* d_out, int out_size) {
    (void)in_sizes; (void)n_in; (void)out_size;
    const float* x     = (const float*)d_in[0];
    const int*   batch = (const int*)d_in[1];
    const float* W1    = (const float*)d_in[2];
    const float* b1    = (const float*)d_in[3];
    const float* W2    = (const float*)d_in[4];
    const float* b2    = (const float*)d_in[5];
    float*       out   = (float*)d_out;

    cudaFuncSetAttribute(scores_kernel,
                         cudaFuncAttributeMaxDynamicSharedMemorySize,
                         SMEM_A_BYTES);

    zseg_kernel<<<BB / 256, 256>>>();
    w1h_kernel<<<DD / 2, HH>>>(W1);
    scores_kernel<<<NN / 128, 256, SMEM_A_BYTES>>>(x, batch, b1, W2, b2);
    pool_kernel<<<BB, 256>>>(x, batch, out);
}

// round 13
// speedup vs baseline: 1.5355x; 1.2268x over previous
#include <cuda_runtime.h>
#include <cuda_fp16.h>
#include <cstdint>

#define NN 524288   // nodes
#define DD 256      // input dim
#define HH 128      // hidden dim
#define BB 2048     // segments

// ---------------- scratch (device globals; no allocation allowed) ----------
__device__ float    g_scores[NN];
__device__ float    g_wts[NN];          // unnormalized exp weights
__device__ float    g_segsum[BB];
__device__ uint32_t g_w1ph[(DD / 2) * HH];  // permuted half2 W1

// ---------------- helpers ---------------------------------------------------
__device__ __forceinline__ float tanha(float x) {
    float y;
    asm("tanh.approx.f32 %0, %1;" : "=f"(y) : "f"(x));
    return y;
}
__device__ __forceinline__ uint32_t smem_u32(const void* p) {
    uint32_t a;
    asm("{ .reg .u64 t; cvta.to.shared.u64 t, %1; cvt.u32.u64 %0, t; }" : "=r"(a) : "l"(p));
    return a;
}
__device__ __forceinline__ uint32_t pack_h2(float lo, float hi) {
    __half2 h = __floats2half2_rn(lo, hi);
    return *(uint32_t*)&h;
}
#define CP16(dst, src)  asm volatile("cp.async.ca.shared.global [%0], [%1], 16;" :: "r"(dst), "l"(src) : "memory")
#define CP_COMMIT()     asm volatile("cp.async.commit_group;" ::: "memory")
#define CP_WAIT(n)      asm volatile("cp.async.wait_group %0;" :: "n"(n) : "memory")

__device__ __forceinline__ void mma_f16(float& c0, float& c1, float& c2, float& c3,
                                        uint32_t a0, uint32_t a1, uint32_t a2, uint32_t a3,
                                        uint32_t b0, uint32_t b1) {
    asm("mma.sync.aligned.m16n8k16.row.col.f32.f16.f16.f32 "
        "{%0,%1,%2,%3}, {%4,%5,%6,%7}, {%8,%9}, {%0,%1,%2,%3};"
        : "+f"(c0), "+f"(c1), "+f"(c2), "+f"(c3)
        : "r"(a0), "r"(a1), "r"(a2), "r"(a3), "r"(b0), "r"(b1));
}

// ---------------- kernel 0: W1 -> permuted packed half2 (one-shot) ---------
__global__ void w1h_kernel(const float* __restrict__ W1) {
    int k2 = blockIdx.x;         // 0..127
    int c  = threadIdx.x;        // 0..127
    g_w1ph[k2 * HH + (c & 7) * 16 + (c >> 3)] =
        pack_h2(W1[(2 * k2) * HH + c], W1[(2 * k2 + 1) * HH + c]);
}

// ---------------- kernel A: scores = tanh(x@W1 + b1) @ W2 + b2 -------------
// EXACT R10 structure. fp16 m16n8k16. 256 threads, 2 CTAs/SM.
// CTA tile: 128 nodes x 128 cols. Warp tile: 32 nodes x 64 cols.
#define KC 32
#define K2C 16
#define XS_STRIDE  20
#define W1P_STRIDE 132
#define XBUF_B  (128 * XS_STRIDE * 4)   // 10240 B
#define W1BUF_B (K2C * W1P_STRIDE * 4)  // 8448 B
#define OFF_X    0
#define OFF_W1   (2 * XBUF_B)            // 20480
#define OFF_B1   (OFF_W1 + 2 * W1BUF_B)  // 37376
#define OFF_W2   (OFF_B1 + 512)
#define OFF_PART (OFF_W2 + 512)
#define OFF_B2   (OFF_PART + 512)
#define SMEM_A_BYTES (OFF_B2 + 16)       // ~38.9 KB (2 CTAs -> ~78 KB/SM)

__global__ void __launch_bounds__(256, 2)
scores_kernel(const float* __restrict__ x,
              const float* __restrict__ b1,
              const float* __restrict__ W2,
              const float* __restrict__ b2) {
    extern __shared__ char smem[];
    const uint32_t sb = smem_u32(smem);

    float* b1s  = (float*)(smem + OFF_B1);
    float* w2s  = (float*)(smem + OFF_W2);
    float* part = (float*)(smem + OFF_PART);

    const int tid  = threadIdx.x;
    const int lane = tid & 31;
    const int wid  = tid >> 5;
    const int t    = lane & 3;          // k2 row within group
    const int g    = lane >> 2;         // group id
    const int wn   = (wid & 3) * 32;    // warp node base
    const int chf  = wid >> 2;          // column half
    const int n0   = blockIdx.x * 128;

    if (tid < 128) { b1s[tid] = b1[tid]; w2s[tid] = W2[tid]; }
    if (tid == 0)  { ((float*)(smem + OFF_B2))[0] = b2[0]; }

    float acc[2][8][4];
    #pragma unroll
    for (int ra = 0; ra < 2; ++ra)
        #pragma unroll
        for (int j = 0; j < 8; ++j)
            #pragma unroll
            for (int r = 0; r < 4; ++r) acc[ra][j][r] = 0.0f;

    const float4* x4   = (const float4*)x;
    const char*   wsrc = (const char*)g_w1ph;

    // staging decompositions
    const int xnode = tid >> 1, xjj = tid & 1;  // x: node, j' = xjj + 2i
    const int wrow  = tid >> 5, wq  = tid & 31; // W1: +tt*8 k2-rows, 16B group

    // ---- prologue: cp.async W1 chunk 0; prefetch x chunk 0 ----
    #pragma unroll
    for (int tt = 0; tt < 2; ++tt) {
        int row = wrow + tt * 8;
        CP16(sb + OFF_W1 + (uint32_t)(row * W1P_STRIDE + 4 * wq) * 4,
             wsrc + (size_t)(row * HH + 4 * wq) * 4);
    }
    CP_COMMIT();

    float4 rx[4];
    #pragma unroll
    for (int i = 0; i < 2; ++i) {
        int jp = xjj + 2 * i;
        rx[2 * i]     = x4[(size_t)(n0 + xnode) * 64 + 2 * jp];
        rx[2 * i + 1] = x4[(size_t)(n0 + xnode) * 64 + 2 * jp + 1];
    }

    for (int ch = 0; ch < 8; ++ch) {
        const int buf = ch & 1;
        uint32_t* xb  = (uint32_t*)(smem + OFF_X  + buf * XBUF_B);
        uint32_t* w1b = (uint32_t*)(smem + OFF_W1 + buf * W1BUF_B);

        // ---- store staged x chunk (cvt to half2, STS.128) ----
        #pragma unroll
        for (int i = 0; i < 2; ++i) {
            int jp = xjj + 2 * i;
            float4 f0 = rx[2 * i], f1 = rx[2 * i + 1];
            uint4 u;
            u.x = pack_h2(f0.x, f0.y); u.y = pack_h2(f0.z, f0.w);
            u.z = pack_h2(f1.x, f1.y); u.w = pack_h2(f1.z, f1.w);
            *(uint4*)(xb + xnode * XS_STRIDE + 4 * jp) = u;
        }

        // ---- issue next chunk's loads ----
        if (ch < 7) {
            const uint32_t wo = OFF_W1 + (buf ^ 1) * W1BUF_B;
            #pragma unroll
            for (int tt = 0; tt < 2; ++tt) {
                int row = wrow + tt * 8;
                CP16(sb + wo + (uint32_t)(row * W1P_STRIDE + 4 * wq) * 4,
                     wsrc + (size_t)(((ch + 1) * K2C + row) * HH + 4 * wq) * 4);
            }
            CP_COMMIT();
            #pragma unroll
            for (int i = 0; i < 2; ++i) {
                int jp = xjj + 2 * i;
                rx[2 * i]     = x4[(size_t)(n0 + xnode) * 64 + (ch + 1) * 8 + 2 * jp];
                rx[2 * i + 1] = x4[(size_t)(n0 + xnode) * 64 + (ch + 1) * 8 + 2 * jp + 1];
            }
            CP_WAIT(1);   // chunk ch's W1 complete; ch+1 in flight
        } else {
            CP_WAIT(0);
        }
        __syncthreads();

        // ---- compute 2 k-steps (K=16 each) ----
        #pragma unroll
        for (int ks = 0; ks < 2; ++ks) {
            const int k2l = ks * 8;
            uint32_t ax[2][4];
            #pragma unroll
            for (int ra = 0; ra < 2; ++ra) {
                const uint32_t* xr = xb + (wn + 16 * ra + g) * XS_STRIDE + k2l;
                ax[ra][0] = xr[t];
                ax[ra][1] = xr[8 * XS_STRIDE + t];
                ax[ra][2] = xr[t + 4];
                ax[ra][3] = xr[8 * XS_STRIDE + t + 4];
            }
            const uint32_t* r0 = w1b + (k2l + t) * W1P_STRIDE + g * 16 + chf * 8;
            const uint32_t* r1 = r0 + 4 * W1P_STRIDE;
            uint4 u0 = *(const uint4*)(r0);
            uint4 u1 = *(const uint4*)(r0 + 4);
            uint4 v0 = *(const uint4*)(r1);
            uint4 v1 = *(const uint4*)(r1 + 4);
            uint32_t bu[8] = {u0.x, u0.y, u0.z, u0.w, u1.x, u1.y, u1.z, u1.w};
            uint32_t bv[8] = {v0.x, v0.y, v0.z, v0.w, v1.x, v1.y, v1.z, v1.w};

            #pragma unroll
            for (int ra = 0; ra < 2; ++ra) {
                #pragma unroll
                for (int j = 0; j < 8; ++j) {
                    mma_f16(acc[ra][j][0], acc[ra][j][1], acc[ra][j][2], acc[ra][j][3],
                            ax[ra][0], ax[ra][1], ax[ra][2], ax[ra][3],
                            bu[j], bv[j]);
                }
            }
        }
        __syncthreads();
    }

    // ---- epilogue: +b1, tanh, dot W2, reduce over t, combine col halves ----
    float p[4] = {0.f, 0.f, 0.f, 0.f};
    #pragma unroll
    for (int ra = 0; ra < 2; ++ra) {
        #pragma unroll
        for (int j = 0; j < 8; ++j) {
            #pragma unroll
            for (int rr = 0; rr < 2; ++rr) {
                int cc = (chf * 8 + j) * 8 + 2 * t + rr;
                float bb = b1s[cc], ww = w2s[cc];
                p[2 * ra]     += tanha(acc[ra][j][rr]     + bb) * ww;
                p[2 * ra + 1] += tanha(acc[ra][j][2 + rr] + bb) * ww;
            }
        }
    }
    #pragma unroll
    for (int i = 0; i < 4; ++i) {
        p[i] += __shfl_xor_sync(0xffffffffu, p[i], 1);
        p[i] += __shfl_xor_sync(0xffffffffu, p[i], 2);
    }
    if (t == 0 && chf == 0) {
        part[wn + g]      = p[0];
        part[wn + g + 8]  = p[1];
        part[wn + g + 16] = p[2];
        part[wn + g + 24] = p[3];
    }
    __syncthreads();
    if (t == 0 && chf == 1) {
        float bb2 = ((float*)(smem + OFF_B2))[0];
        g_scores[n0 + wn + g]      = part[wn + g]      + p[0] + bb2;
        g_scores[n0 + wn + g + 8]  = part[wn + g + 8]  + p[1] + bb2;
        g_scores[n0 + wn + g + 16] = part[wn + g + 16] + p[2] + bb2;
        g_scores[n0 + wn + g + 24] = part[wn + g + 24] + p[3] + bb2;
    }
}

// ---------------- binary search ---------------------------------------------
__device__ __forceinline__ int lower_bound_i32(const int* __restrict__ a, int n, int v) {
    int lo = 0, hi = n;
    while (lo < hi) {
        int mid = (lo + hi) >> 1;
        if (a[mid] < v) lo = mid + 1; else hi = mid;
    }
    return lo;
}

// ---------------- kernel B: per-segment max + exp weights + sum -------------
__global__ void segstats_kernel(const int* __restrict__ batch) {
    const int b = blockIdx.x;
    const int tid = threadIdx.x;
    __shared__ int se[2];
    __shared__ float red[256];

    if (tid == 0) {
        se[0] = lower_bound_i32(batch, NN, b);
        se[1] = lower_bound_i32(batch, NN, b + 1);
    }
    __syncthreads();
    const int st = se[0], en = se[1];

    float m = -1e30f;
    for (int i = st + tid; i < en; i += 256) m = fmaxf(m, g_scores[i]);
    red[tid] = m;
    __syncthreads();
    #pragma unroll
    for (int off = 128; off > 0; off >>= 1) {
        if (tid < off) red[tid] = fmaxf(red[tid], red[tid + off]);
        __syncthreads();
    }
    m = red[0];
    __syncthreads();

    float z = 0.0f;
    for (int i = st + tid; i < en; i += 256) {
        float e = expf(g_scores[i] - m);
        g_wts[i] = e;
        z += e;
    }
    red[tid] = z;
    __syncthreads();
    #pragma unroll
    for (int off = 128; off > 0; off >>= 1) {
        if (tid < off) red[tid] += red[tid + off];
        __syncthreads();
    }
    if (tid == 0) g_segsum[b] = (en > st) ? red[0] : 0.0f;
}

// ---------------- kernel C: pooled[b,d] = sum_i x[i,d] * w_i  (MLP=16) ------
__global__ void pool_kernel(const float* __restrict__ x,
                            const int* __restrict__ batch,
                            float* __restrict__ out) {
    const int b = blockIdx.x;
    const int tid = threadIdx.x;   // dim d
    __shared__ int se[2];
    __shared__ float ws[256];

    if (tid == 0) {
        se[0] = lower_bound_i32(batch, NN, b);
        se[1] = lower_bound_i32(batch, NN, b + 1);
    }
    __syncthreads();
    const int st = se[0], en = se[1];
    const float Z = g_segsum[b];
    const float invZ = (en > st && Z > 0.0f) ? (1.0f / Z) : 0.0f;

    float acc = 0.0f;
    for (int i0 = st; i0 < en; i0 += 256) {
        int cnt = min(256, en - i0);
        __syncthreads();
        if (tid < cnt) ws[tid] = g_wts[i0 + tid] * invZ;
        __syncthreads();
        const float* xp = x + (size_t)i0 * DD + tid;
        int j = 0;
        // 16-deep front-batched loads (MLP=16)
        for (; j + 16 <= cnt; j += 16) {
            float v[16];
            #pragma unroll
            for (int q = 0; q < 16; ++q) v[q] = xp[(size_t)(j + q) * DD];
            #pragma unroll
            for (int q = 0; q < 16; ++q) acc += v[q] * ws[j + q];
        }
        for (; j + 8 <= cnt; j += 8) {
            float v[8];
            #pragma unroll
            for (int q = 0; q < 8; ++q) v[q] = xp[(size_t)(j + q) * DD];
            #pragma unroll
            for (int q = 0; q < 8; ++q) acc += v[q] * ws[j + q];
        }
        for (; j < cnt; ++j) acc += xp[(size_t)j * DD] * ws[j];
    }
    out[(size_t)b * DD + tid] = acc;
}

// ---------------- launch ------------------------------------------------------
extern "C" void kernel_launch(void* const* d_in, const int* in_sizes, int n_in,
                              void* d_out, int out_size) {
    (void)in_sizes; (void)n_in; (void)out_size;
    const float* x     = (const float*)d_in[0];
    const int*   batch = (const int*)d_in[1];
    const float* W1    = (const float*)d_in[2];
    const float* b1    = (const float*)d_in[3];
    const float* W2    = (const float*)d_in[4];
    const float* b2    = (const float*)d_in[5];
    float*       out   = (float*)d_out;

    cudaFuncSetAttribute(scores_kernel,
                         cudaFuncAttributeMaxDynamicSharedMemorySize,
                         SMEM_A_BYTES);

    w1h_kernel<<<DD / 2, HH>>>(W1);
    scores_kernel<<<NN / 128, 256, SMEM_A_BYTES>>>(x, b1, W2, b2);
    segstats_kernel<<<BB, 256>>>(batch);
    pool_kernel<<<BB, 256>>>(x, batch, out);
}

// round 14
// speedup vs baseline: 1.6396x; 1.0678x over previous
#include <cuda_runtime.h>
#include <cuda_fp16.h>
#include <cstdint>

#define NN 524288   // nodes
#define DD 256      // input dim
#define HH 128      // hidden dim
#define BB 2048     // segments

// ---------------- scratch (device globals; no allocation allowed) ----------
__device__ float    g_scores[NN];
__device__ uint32_t g_w1ph[(DD / 2) * HH];  // permuted half2 W1

// ---------------- helpers ---------------------------------------------------
__device__ __forceinline__ float tanha(float x) {
    float y;
    asm("tanh.approx.f32 %0, %1;" : "=f"(y) : "f"(x));
    return y;
}
__device__ __forceinline__ uint32_t smem_u32(const void* p) {
    uint32_t a;
    asm("{ .reg .u64 t; cvta.to.shared.u64 t, %1; cvt.u32.u64 %0, t; }" : "=r"(a) : "l"(p));
    return a;
}
__device__ __forceinline__ uint32_t pack_h2(float lo, float hi) {
    __half2 h = __floats2half2_rn(lo, hi);
    return *(uint32_t*)&h;
}
#define CP16(dst, src)  asm volatile("cp.async.ca.shared.global [%0], [%1], 16;" :: "r"(dst), "l"(src) : "memory")
#define CP_COMMIT()     asm volatile("cp.async.commit_group;" ::: "memory")
#define CP_WAIT(n)      asm volatile("cp.async.wait_group %0;" :: "n"(n) : "memory")

__device__ __forceinline__ void mma_f16(float& c0, float& c1, float& c2, float& c3,
                                        uint32_t a0, uint32_t a1, uint32_t a2, uint32_t a3,
                                        uint32_t b0, uint32_t b1) {
    asm("mma.sync.aligned.m16n8k16.row.col.f32.f16.f16.f32 "
        "{%0,%1,%2,%3}, {%4,%5,%6,%7}, {%8,%9}, {%0,%1,%2,%3};"
        : "+f"(c0), "+f"(c1), "+f"(c2), "+f"(c3)
        : "r"(a0), "r"(a1), "r"(a2), "r"(a3), "r"(b0), "r"(b1));
}

__device__ __forceinline__ void ldsm_x4(uint32_t& r0, uint32_t& r1, uint32_t& r2, uint32_t& r3,
                                        uint32_t addr) {
    asm volatile("ldmatrix.sync.aligned.m8n8.x4.shared.b16 {%0,%1,%2,%3}, [%4];"
                 : "=r"(r0), "=r"(r1), "=r"(r2), "=r"(r3) : "r"(addr));
}

// ---------------- kernel 0: W1 -> permuted packed half2 (one-shot) ---------
__global__ void w1h_kernel(const float* __restrict__ W1) {
    int k2 = blockIdx.x;         // 0..127
    int c  = threadIdx.x;        // 0..127
    g_w1ph[k2 * HH + (c & 7) * 16 + (c >> 3)] =
        pack_h2(W1[(2 * k2) * HH + c], W1[(2 * k2 + 1) * HH + c]);
}

// ---------------- kernel A: scores = tanh(x@W1 + b1) @ W2 + b2 -------------
// R10 structure + ldmatrix A-fragments. fp16 m16n8k16. 256 threads, 2 CTAs/SM.
// CTA tile: 128 nodes x 128 cols. Warp tile: 32 nodes x 64 cols.
#define KC 32
#define K2C 16
#define XS_STRIDE  20
#define W1P_STRIDE 132
#define XBUF_B  (128 * XS_STRIDE * 4)   // 10240 B
#define W1BUF_B (K2C * W1P_STRIDE * 4)  // 8448 B
#define OFF_X    0
#define OFF_W1   (2 * XBUF_B)            // 20480
#define OFF_B1   (OFF_W1 + 2 * W1BUF_B)  // 37376
#define OFF_W2   (OFF_B1 + 512)
#define OFF_PART (OFF_W2 + 512)
#define OFF_B2   (OFF_PART + 512)
#define SMEM_A_BYTES (OFF_B2 + 16)       // ~38.9 KB (2 CTAs -> ~78 KB/SM)

__global__ void __launch_bounds__(256, 2)
scores_kernel(const float* __restrict__ x,
              const float* __restrict__ b1,
              const float* __restrict__ W2,
              const float* __restrict__ b2) {
    extern __shared__ char smem[];
    const uint32_t sb = smem_u32(smem);

    float* b1s  = (float*)(smem + OFF_B1);
    float* w2s  = (float*)(smem + OFF_W2);
    float* part = (float*)(smem + OFF_PART);

    const int tid  = threadIdx.x;
    const int lane = tid & 31;
    const int wid  = tid >> 5;
    const int t    = lane & 3;          // k2 row within group
    const int g    = lane >> 2;         // group id
    const int wn   = (wid & 3) * 32;    // warp node base
    const int chf  = wid >> 2;          // column half
    const int n0   = blockIdx.x * 128;

    if (tid < 128) { b1s[tid] = b1[tid]; w2s[tid] = W2[tid]; }
    if (tid == 0)  { ((float*)(smem + OFF_B2))[0] = b2[0]; }

    float acc[2][8][4];
    #pragma unroll
    for (int ra = 0; ra < 2; ++ra)
        #pragma unroll
        for (int j = 0; j < 8; ++j)
            #pragma unroll
            for (int r = 0; r < 4; ++r) acc[ra][j][r] = 0.0f;

    const float4* x4   = (const float4*)x;
    const char*   wsrc = (const char*)g_w1ph;

    // staging decompositions
    const int xnode = tid >> 1, xjj = tid & 1;  // x: node, j' = xjj + 2i
    const int wrow  = tid >> 5, wq  = tid & 31; // W1: +tt*8 k2-rows, 16B group

    // ldmatrix per-lane address pieces: row = wn + 16*ra + (lane&15),
    // col-half byte offset = (lane>>4)*16; +k2l*4 per kstep.
    const uint32_t lm_row  = (uint32_t)(wn + (lane & 15)) * (XS_STRIDE * 4)
                           + (uint32_t)(lane >> 4) * 16;

    // ---- prologue: cp.async W1 chunk 0; prefetch x chunk 0 ----
    #pragma unroll
    for (int tt = 0; tt < 2; ++tt) {
        int row = wrow + tt * 8;
        CP16(sb + OFF_W1 + (uint32_t)(row * W1P_STRIDE + 4 * wq) * 4,
             wsrc + (size_t)(row * HH + 4 * wq) * 4);
    }
    CP_COMMIT();

    float4 rx[4];
    #pragma unroll
    for (int i = 0; i < 2; ++i) {
        int jp = xjj + 2 * i;
        rx[2 * i]     = x4[(size_t)(n0 + xnode) * 64 + 2 * jp];
        rx[2 * i + 1] = x4[(size_t)(n0 + xnode) * 64 + 2 * jp + 1];
    }

    for (int ch = 0; ch < 8; ++ch) {
        const int buf = ch & 1;
        uint32_t* xb  = (uint32_t*)(smem + OFF_X  + buf * XBUF_B);
        uint32_t* w1b = (uint32_t*)(smem + OFF_W1 + buf * W1BUF_B);
        const uint32_t xb_u32 = sb + OFF_X + buf * XBUF_B;

        // ---- store staged x chunk (cvt to half2, STS.128) ----
        #pragma unroll
        for (int i = 0; i < 2; ++i) {
            int jp = xjj + 2 * i;
            float4 f0 = rx[2 * i], f1 = rx[2 * i + 1];
            uint4 u;
            u.x = pack_h2(f0.x, f0.y); u.y = pack_h2(f0.z, f0.w);
            u.z = pack_h2(f1.x, f1.y); u.w = pack_h2(f1.z, f1.w);
            *(uint4*)(xb + xnode * XS_STRIDE + 4 * jp) = u;
        }

        // ---- issue next chunk's loads ----
        if (ch < 7) {
            const uint32_t wo = OFF_W1 + (buf ^ 1) * W1BUF_B;
            #pragma unroll
            for (int tt = 0; tt < 2; ++tt) {
                int row = wrow + tt * 8;
                CP16(sb + wo + (uint32_t)(row * W1P_STRIDE + 4 * wq) * 4,
                     wsrc + (size_t)(((ch + 1) * K2C + row) * HH + 4 * wq) * 4);
            }
            CP_COMMIT();
            #pragma unroll
            for (int i = 0; i < 2; ++i) {
                int jp = xjj + 2 * i;
                rx[2 * i]     = x4[(size_t)(n0 + xnode) * 64 + (ch + 1) * 8 + 2 * jp];
                rx[2 * i + 1] = x4[(size_t)(n0 + xnode) * 64 + (ch + 1) * 8 + 2 * jp + 1];
            }
            CP_WAIT(1);   // chunk ch's W1 complete; ch+1 in flight
        } else {
            CP_WAIT(0);
        }
        __syncthreads();

        // ---- compute 2 k-steps (K=16 each) ----
        #pragma unroll
        for (int ks = 0; ks < 2; ++ks) {
            const int k2l = ks * 8;
            // A fragments via ldmatrix.x4 (1 instr per 16x16 tile)
            uint32_t ax[2][4];
            #pragma unroll
            for (int ra = 0; ra < 2; ++ra) {
                uint32_t addr = xb_u32 + lm_row
                              + (uint32_t)(16 * ra) * (XS_STRIDE * 4)
                              + (uint32_t)(k2l * 4);
                ldsm_x4(ax[ra][0], ax[ra][1], ax[ra][2], ax[ra][3], addr);
            }
            // B fragments: 4 LDS.128 (conflict-free)
            const uint32_t* r0 = w1b + (k2l + t) * W1P_STRIDE + g * 16 + chf * 8;
            const uint32_t* r1 = r0 + 4 * W1P_STRIDE;
            uint4 u0 = *(const uint4*)(r0);
            uint4 u1 = *(const uint4*)(r0 + 4);
            uint4 v0 = *(const uint4*)(r1);
            uint4 v1 = *(const uint4*)(r1 + 4);
            uint32_t bu[8] = {u0.x, u0.y, u0.z, u0.w, u1.x, u1.y, u1.z, u1.w};
            uint32_t bv[8] = {v0.x, v0.y, v0.z, v0.w, v1.x, v1.y, v1.z, v1.w};

            #pragma unroll
            for (int ra = 0; ra < 2; ++ra) {
                #pragma unroll
                for (int j = 0; j < 8; ++j) {
                    mma_f16(acc[ra][j][0], acc[ra][j][1], acc[ra][j][2], acc[ra][j][3],
                            ax[ra][0], ax[ra][1], ax[ra][2], ax[ra][3],
                            bu[j], bv[j]);
                }
            }
        }
        __syncthreads();
    }

    // ---- epilogue: +b1, tanh, dot W2, reduce over t, combine col halves ----
    float p[4] = {0.f, 0.f, 0.f, 0.f};
    #pragma unroll
    for (int ra = 0; ra < 2; ++ra) {
        #pragma unroll
        for (int j = 0; j < 8; ++j) {
            #pragma unroll
            for (int rr = 0; rr < 2; ++rr) {
                int cc = (chf * 8 + j) * 8 + 2 * t + rr;
                float bb = b1s[cc], ww = w2s[cc];
                p[2 * ra]     += tanha(acc[ra][j][rr]     + bb) * ww;
                p[2 * ra + 1] += tanha(acc[ra][j][2 + rr] + bb) * ww;
            }
        }
    }
    #pragma unroll
    for (int i = 0; i < 4; ++i) {
        p[i] += __shfl_xor_sync(0xffffffffu, p[i], 1);
        p[i] += __shfl_xor_sync(0xffffffffu, p[i], 2);
    }
    if (t == 0 && chf == 0) {
        part[wn + g]      = p[0];
        part[wn + g + 8]  = p[1];
        part[wn + g + 16] = p[2];
        part[wn + g + 24] = p[3];
    }
    __syncthreads();
    if (t == 0 && chf == 1) {
        float bb2 = ((float*)(smem + OFF_B2))[0];
        g_scores[n0 + wn + g]      = part[wn + g]      + p[0] + bb2;
        g_scores[n0 + wn + g + 8]  = part[wn + g + 8]  + p[1] + bb2;
        g_scores[n0 + wn + g + 16] = part[wn + g + 16] + p[2] + bb2;
        g_scores[n0 + wn + g + 24] = part[wn + g + 24] + p[3] + bb2;
    }
}

// ---------------- binary search ---------------------------------------------
__device__ __forceinline__ int lower_bound_i32(const int* __restrict__ a, int n, int v) {
    int lo = 0, hi = n;
    while (lo < hi) {
        int mid = (lo + hi) >> 1;
        if (a[mid] < v) lo = mid + 1; else hi = mid;
    }
    return lo;
}

// ---------------- kernel C: fused segstats + pooling -------------------------
// Per segment: compute max, Z inline (scores are L2-hot), then weighted sum.
__global__ void pool_kernel(const float* __restrict__ x,
                            const int* __restrict__ batch,
                            float* __restrict__ out) {
    const int b = blockIdx.x;
    const int tid = threadIdx.x;   // dim d
    __shared__ int se[2];
    __shared__ float red[256];
    __shared__ float ws[256];

    if (tid == 0) {
        se[0] = lower_bound_i32(batch, NN, b);
        se[1] = lower_bound_i32(batch, NN, b + 1);
    }
    __syncthreads();
    const int st = se[0], en = se[1];

    // pass 1: segment max
    float m = -1e30f;
    for (int i = st + tid; i < en; i += 256) m = fmaxf(m, g_scores[i]);
    red[tid] = m;
    __syncthreads();
    #pragma unroll
    for (int off = 128; off > 0; off >>= 1) {
        if (tid < off) red[tid] = fmaxf(red[tid], red[tid + off]);
        __syncthreads();
    }
    m = red[0];
    __syncthreads();

    // pass 2: Z = sum exp
    float z = 0.0f;
    for (int i = st + tid; i < en; i += 256) z += expf(g_scores[i] - m);
    red[tid] = z;
    __syncthreads();
    #pragma unroll
    for (int off = 128; off > 0; off >>= 1) {
        if (tid < off) red[tid] += red[tid + off];
        __syncthreads();
    }
    const float Z = red[0];
    const float invZ = (en > st && Z > 0.0f) ? (1.0f / Z) : 0.0f;
    __syncthreads();

    // pass 3: weighted pooling (R5 form)
    float acc = 0.0f;
    for (int i0 = st; i0 < en; i0 += 256) {
        int cnt = min(256, en - i0);
        __syncthreads();
        if (tid < cnt) ws[tid] = expf(g_scores[i0 + tid] - m) * invZ;
        __syncthreads();
        const float* xp = x + (size_t)i0 * DD + tid;
        int j = 0;
        for (; j + 8 <= cnt; j += 8) {
            float v0 = xp[(size_t)(j + 0) * DD];
            float v1 = xp[(size_t)(j + 1) * DD];
            float v2 = xp[(size_t)(j + 2) * DD];
            float v3 = xp[(size_t)(j + 3) * DD];
            float v4 = xp[(size_t)(j + 4) * DD];
            float v5 = xp[(size_t)(j + 5) * DD];
            float v6 = xp[(size_t)(j + 6) * DD];
            float v7 = xp[(size_t)(j + 7) * DD];
            acc += v0 * ws[j + 0]; acc += v1 * ws[j + 1];
            acc += v2 * ws[j + 2]; acc += v3 * ws[j + 3];
            acc += v4 * ws[j + 4]; acc += v5 * ws[j + 5];
            acc += v6 * ws[j + 6]; acc += v7 * ws[j + 7];
        }
        for (; j < cnt; ++j) acc += xp[(size_t)j * DD] * ws[j];
    }
    out[(size_t)b * DD + tid] = acc;
}

// ---------------- launch ------------------------------------------------------
extern "C" void kernel_launch(void* const* d_in, const int* in_sizes, int n_in,
                              void* d_out, int out_size) {
    (void)in_sizes; (void)n_in; (void)out_size;
    const float* x     = (const float*)d_in[0];
    const int*   batch = (const int*)d_in[1];
    const float* W1    = (const float*)d_in[2];
    const float* b1    = (const float*)d_in[3];
    const float* W2    = (const float*)d_in[4];
    const float* b2    = (const float*)d_in[5];
    float*       out   = (float*)d_out;

    cudaFuncSetAttribute(scores_kernel,
                         cudaFuncAttributeMaxDynamicSharedMemorySize,
                         SMEM_A_BYTES);

    w1h_kernel<<<DD / 2, HH>>>(W1);
    scores_kernel<<<NN / 128, 256, SMEM_A_BYTES>>>(x, b1, W2, b2);
    pool_kernel<<<BB, 256>>>(x, batch, out);
}

// round 15
// speedup vs baseline: 1.6558x; 1.0099x over previous
#include <cuda_runtime.h>
#include <cuda_fp16.h>
#include <cstdint>

#define NN 524288   // nodes
#define DD 256      // input dim
#define HH 128      // hidden dim
#define BB 2048     // segments

// ---------------- scratch (device globals; no allocation allowed) ----------
__device__ float    g_scores[NN];
__device__ uint32_t g_w1ph[(DD / 2) * HH];  // permuted half2 W1

// ---------------- helpers ---------------------------------------------------
__device__ __forceinline__ float tanha(float x) {
    float y;
    asm("tanh.approx.f32 %0, %1;" : "=f"(y) : "f"(x));
    return y;
}
__device__ __forceinline__ uint32_t smem_u32(const void* p) {
    uint32_t a;
    asm("{ .reg .u64 t; cvta.to.shared.u64 t, %1; cvt.u32.u64 %0, t; }" : "=r"(a) : "l"(p));
    return a;
}
__device__ __forceinline__ uint32_t pack_h2(float lo, float hi) {
    __half2 h = __floats2half2_rn(lo, hi);
    return *(uint32_t*)&h;
}
#define CP16(dst, src)  asm volatile("cp.async.ca.shared.global [%0], [%1], 16;" :: "r"(dst), "l"(src) : "memory")
#define CP_COMMIT()     asm volatile("cp.async.commit_group;" ::: "memory")
#define CP_WAIT(n)      asm volatile("cp.async.wait_group %0;" :: "n"(n) : "memory")

__device__ __forceinline__ void mma_f16(float& c0, float& c1, float& c2, float& c3,
                                        uint32_t a0, uint32_t a1, uint32_t a2, uint32_t a3,
                                        uint32_t b0, uint32_t b1) {
    asm("mma.sync.aligned.m16n8k16.row.col.f32.f16.f16.f32 "
        "{%0,%1,%2,%3}, {%4,%5,%6,%7}, {%8,%9}, {%0,%1,%2,%3};"
        : "+f"(c0), "+f"(c1), "+f"(c2), "+f"(c3)
        : "r"(a0), "r"(a1), "r"(a2), "r"(a3), "r"(b0), "r"(b1));
}

__device__ __forceinline__ void ldsm_x4(uint32_t& r0, uint32_t& r1, uint32_t& r2, uint32_t& r3,
                                        uint32_t addr) {
    asm volatile("ldmatrix.sync.aligned.m8n8.x4.shared.b16 {%0,%1,%2,%3}, [%4];"
                 : "=r"(r0), "=r"(r1), "=r"(r2), "=r"(r3) : "r"(addr));
}

// ---------------- kernel 0: W1 -> permuted packed half2 (one-shot) ---------
__global__ void w1h_kernel(const float* __restrict__ W1) {
    int k2 = blockIdx.x;         // 0..127
    int c  = threadIdx.x;        // 0..127
    g_w1ph[k2 * HH + (c & 7) * 16 + (c >> 3)] =
        pack_h2(W1[(2 * k2) * HH + c], W1[(2 * k2 + 1) * HH + c]);
}

// ---------------- kernel A: scores = tanh(x@W1 + b1) @ W2 + b2 -------------
// R14 version (unchanged): fp16 m16n8k16, ldmatrix A-frags, cp.async W1.
// 256 threads, 2 CTAs/SM. CTA tile: 128 nodes x 128 cols. Warp: 32x64.
#define KC 32
#define K2C 16
#define XS_STRIDE  20
#define W1P_STRIDE 132
#define XBUF_B  (128 * XS_STRIDE * 4)   // 10240 B
#define W1BUF_B (K2C * W1P_STRIDE * 4)  // 8448 B
#define OFF_X    0
#define OFF_W1   (2 * XBUF_B)            // 20480
#define OFF_B1   (OFF_W1 + 2 * W1BUF_B)  // 37376
#define OFF_W2   (OFF_B1 + 512)
#define OFF_PART (OFF_W2 + 512)
#define OFF_B2   (OFF_PART + 512)
#define SMEM_A_BYTES (OFF_B2 + 16)       // ~38.9 KB (2 CTAs -> ~78 KB/SM)

__global__ void __launch_bounds__(256, 2)
scores_kernel(const float* __restrict__ x,
              const float* __restrict__ b1,
              const float* __restrict__ W2,
              const float* __restrict__ b2) {
    extern __shared__ char smem[];
    const uint32_t sb = smem_u32(smem);

    float* b1s  = (float*)(smem + OFF_B1);
    float* w2s  = (float*)(smem + OFF_W2);
    float* part = (float*)(smem + OFF_PART);

    const int tid  = threadIdx.x;
    const int lane = tid & 31;
    const int wid  = tid >> 5;
    const int t    = lane & 3;          // k2 row within group
    const int g    = lane >> 2;         // group id
    const int wn   = (wid & 3) * 32;    // warp node base
    const int chf  = wid >> 2;          // column half
    const int n0   = blockIdx.x * 128;

    if (tid < 128) { b1s[tid] = b1[tid]; w2s[tid] = W2[tid]; }
    if (tid == 0)  { ((float*)(smem + OFF_B2))[0] = b2[0]; }

    float acc[2][8][4];
    #pragma unroll
    for (int ra = 0; ra < 2; ++ra)
        #pragma unroll
        for (int j = 0; j < 8; ++j)
            #pragma unroll
            for (int r = 0; r < 4; ++r) acc[ra][j][r] = 0.0f;

    const float4* x4   = (const float4*)x;
    const char*   wsrc = (const char*)g_w1ph;

    // staging decompositions
    const int xnode = tid >> 1, xjj = tid & 1;  // x: node, j' = xjj + 2i
    const int wrow  = tid >> 5, wq  = tid & 31; // W1: +tt*8 k2-rows, 16B group

    // ldmatrix per-lane address pieces
    const uint32_t lm_row  = (uint32_t)(wn + (lane & 15)) * (XS_STRIDE * 4)
                           + (uint32_t)(lane >> 4) * 16;

    // ---- prologue: cp.async W1 chunk 0; prefetch x chunk 0 ----
    #pragma unroll
    for (int tt = 0; tt < 2; ++tt) {
        int row = wrow + tt * 8;
        CP16(sb + OFF_W1 + (uint32_t)(row * W1P_STRIDE + 4 * wq) * 4,
             wsrc + (size_t)(row * HH + 4 * wq) * 4);
    }
    CP_COMMIT();

    float4 rx[4];
    #pragma unroll
    for (int i = 0; i < 2; ++i) {
        int jp = xjj + 2 * i;
        rx[2 * i]     = x4[(size_t)(n0 + xnode) * 64 + 2 * jp];
        rx[2 * i + 1] = x4[(size_t)(n0 + xnode) * 64 + 2 * jp + 1];
    }

    for (int ch = 0; ch < 8; ++ch) {
        const int buf = ch & 1;
        uint32_t* xb  = (uint32_t*)(smem + OFF_X  + buf * XBUF_B);
        uint32_t* w1b = (uint32_t*)(smem + OFF_W1 + buf * W1BUF_B);
        const uint32_t xb_u32 = sb + OFF_X + buf * XBUF_B;

        // ---- store staged x chunk (cvt to half2, STS.128) ----
        #pragma unroll
        for (int i = 0; i < 2; ++i) {
            int jp = xjj + 2 * i;
            float4 f0 = rx[2 * i], f1 = rx[2 * i + 1];
            uint4 u;
            u.x = pack_h2(f0.x, f0.y); u.y = pack_h2(f0.z, f0.w);
            u.z = pack_h2(f1.x, f1.y); u.w = pack_h2(f1.z, f1.w);
            *(uint4*)(xb + xnode * XS_STRIDE + 4 * jp) = u;
        }

        // ---- issue next chunk's loads ----
        if (ch < 7) {
            const uint32_t wo = OFF_W1 + (buf ^ 1) * W1BUF_B;
            #pragma unroll
            for (int tt = 0; tt < 2; ++tt) {
                int row = wrow + tt * 8;
                CP16(sb + wo + (uint32_t)(row * W1P_STRIDE + 4 * wq) * 4,
                     wsrc + (size_t)(((ch + 1) * K2C + row) * HH + 4 * wq) * 4);
            }
            CP_COMMIT();
            #pragma unroll
            for (int i = 0; i < 2; ++i) {
                int jp = xjj + 2 * i;
                rx[2 * i]     = x4[(size_t)(n0 + xnode) * 64 + (ch + 1) * 8 + 2 * jp];
                rx[2 * i + 1] = x4[(size_t)(n0 + xnode) * 64 + (ch + 1) * 8 + 2 * jp + 1];
            }
            CP_WAIT(1);   // chunk ch's W1 complete; ch+1 in flight
        } else {
            CP_WAIT(0);
        }
        __syncthreads();

        // ---- compute 2 k-steps (K=16 each) ----
        #pragma unroll
        for (int ks = 0; ks < 2; ++ks) {
            const int k2l = ks * 8;
            uint32_t ax[2][4];
            #pragma unroll
            for (int ra = 0; ra < 2; ++ra) {
                uint32_t addr = xb_u32 + lm_row
                              + (uint32_t)(16 * ra) * (XS_STRIDE * 4)
                              + (uint32_t)(k2l * 4);
                ldsm_x4(ax[ra][0], ax[ra][1], ax[ra][2], ax[ra][3], addr);
            }
            const uint32_t* r0 = w1b + (k2l + t) * W1P_STRIDE + g * 16 + chf * 8;
            const uint32_t* r1 = r0 + 4 * W1P_STRIDE;
            uint4 u0 = *(const uint4*)(r0);
            uint4 u1 = *(const uint4*)(r0 + 4);
            uint4 v0 = *(const uint4*)(r1);
            uint4 v1 = *(const uint4*)(r1 + 4);
            uint32_t bu[8] = {u0.x, u0.y, u0.z, u0.w, u1.x, u1.y, u1.z, u1.w};
            uint32_t bv[8] = {v0.x, v0.y, v0.z, v0.w, v1.x, v1.y, v1.z, v1.w};

            #pragma unroll
            for (int ra = 0; ra < 2; ++ra) {
                #pragma unroll
                for (int j = 0; j < 8; ++j) {
                    mma_f16(acc[ra][j][0], acc[ra][j][1], acc[ra][j][2], acc[ra][j][3],
                            ax[ra][0], ax[ra][1], ax[ra][2], ax[ra][3],
                            bu[j], bv[j]);
                }
            }
        }
        __syncthreads();
    }

    // ---- epilogue: +b1, tanh, dot W2, reduce over t, combine col halves ----
    float p[4] = {0.f, 0.f, 0.f, 0.f};
    #pragma unroll
    for (int ra = 0; ra < 2; ++ra) {
        #pragma unroll
        for (int j = 0; j < 8; ++j) {
            #pragma unroll
            for (int rr = 0; rr < 2; ++rr) {
                int cc = (chf * 8 + j) * 8 + 2 * t + rr;
                float bb = b1s[cc], ww = w2s[cc];
                p[2 * ra]     += tanha(acc[ra][j][rr]     + bb) * ww;
                p[2 * ra + 1] += tanha(acc[ra][j][2 + rr] + bb) * ww;
            }
        }
    }
    #pragma unroll
    for (int i = 0; i < 4; ++i) {
        p[i] += __shfl_xor_sync(0xffffffffu, p[i], 1);
        p[i] += __shfl_xor_sync(0xffffffffu, p[i], 2);
    }
    if (t == 0 && chf == 0) {
        part[wn + g]      = p[0];
        part[wn + g + 8]  = p[1];
        part[wn + g + 16] = p[2];
        part[wn + g + 24] = p[3];
    }
    __syncthreads();
    if (t == 0 && chf == 1) {
        float bb2 = ((float*)(smem + OFF_B2))[0];
        g_scores[n0 + wn + g]      = part[wn + g]      + p[0] + bb2;
        g_scores[n0 + wn + g + 8]  = part[wn + g + 8]  + p[1] + bb2;
        g_scores[n0 + wn + g + 16] = part[wn + g + 16] + p[2] + bb2;
        g_scores[n0 + wn + g + 24] = part[wn + g + 24] + p[3] + bb2;
    }
}

// ---------------- binary search ---------------------------------------------
__device__ __forceinline__ int lower_bound_i32(const int* __restrict__ a, int n, int v) {
    int lo = 0, hi = n;
    while (lo < hi) {
        int mid = (lo + hi) >> 1;
        if (a[mid] < v) lo = mid + 1; else hi = mid;
    }
    return lo;
}

// ---------------- kernel C: fused softmax + pooling (2 passes) --------------
// Scores bounded (|score| <= ~11.4) -> unshifted exp is f32-safe (validated
// R11/R12). Pass 1: Z = sum exp. Pass 2: weighted pooling.
__global__ void pool_kernel(const float* __restrict__ x,
                            const int* __restrict__ batch,
                            float* __restrict__ out) {
    const int b = blockIdx.x;
    const int tid = threadIdx.x;   // dim d
    __shared__ int se[2];
    __shared__ float red[256];
    __shared__ float ws[256];

    if (tid == 0) {
        se[0] = lower_bound_i32(batch, NN, b);
        se[1] = lower_bound_i32(batch, NN, b + 1);
    }
    __syncthreads();
    const int st = se[0], en = se[1];

    // pass 1: Z = sum of unshifted exp
    float z = 0.0f;
    for (int i = st + tid; i < en; i += 256) z += expf(g_scores[i]);
    red[tid] = z;
    __syncthreads();
    #pragma unroll
    for (int off = 128; off > 0; off >>= 1) {
        if (tid < off) red[tid] += red[tid + off];
        __syncthreads();
    }
    const float Z = red[0];
    const float invZ = (en > st && Z > 0.0f) ? (1.0f / Z) : 0.0f;
    __syncthreads();

    // pass 2: weighted pooling
    float acc = 0.0f;
    for (int i0 = st; i0 < en; i0 += 256) {
        int cnt = min(256, en - i0);
        __syncthreads();
        if (tid < cnt) ws[tid] = expf(g_scores[i0 + tid]) * invZ;
        __syncthreads();
        const float* xp = x + (size_t)i0 * DD + tid;
        int j = 0;
        for (; j + 8 <= cnt; j += 8) {
            float v0 = xp[(size_t)(j + 0) * DD];
            float v1 = xp[(size_t)(j + 1) * DD];
            float v2 = xp[(size_t)(j + 2) * DD];
            float v3 = xp[(size_t)(j + 3) * DD];
            float v4 = xp[(size_t)(j + 4) * DD];
            float v5 = xp[(size_t)(j + 5) * DD];
            float v6 = xp[(size_t)(j + 6) * DD];
            float v7 = xp[(size_t)(j + 7) * DD];
            acc += v0 * ws[j + 0]; acc += v1 * ws[j + 1];
            acc += v2 * ws[j + 2]; acc += v3 * ws[j + 3];
            acc += v4 * ws[j + 4]; acc += v5 * ws[j + 5];
            acc += v6 * ws[j + 6]; acc += v7 * ws[j + 7];
        }
        for (; j < cnt; ++j) acc += xp[(size_t)j * DD] * ws[j];
    }
    out[(size_t)b * DD + tid] = acc;
}

// ---------------- launch ------------------------------------------------------
extern "C" void kernel_launch(void* const* d_in, const int* in_sizes, int n_in,
                              void* d_out, int out_size) {
    (void)in_sizes; (void)n_in; (void)out_size;
    const float* x     = (const float*)d_in[0];
    const int*   batch = (const int*)d_in[1];
    const float* W1    = (const float*)d_in[2];
    const float* b1    = (const float*)d_in[3];
    const float* W2    = (const float*)d_in[4];
    const float* b2    = (const float*)d_in[5];
    float*       out   = (float*)d_out;

    cudaFuncSetAttribute(scores_kernel,
                         cudaFuncAttributeMaxDynamicSharedMemorySize,
                         SMEM_A_BYTES);

    w1h_kernel<<<DD / 2, HH>>>(W1);
    scores_kernel<<<NN / 128, 256, SMEM_A_BYTES>>>(x, b1, W2, b2);
    pool_kernel<<<BB, 256>>>(x, batch, out);
}